// round 9
// baseline (speedup 1.0000x reference)
#include <cuda_runtime.h>
#include <math.h>
#include <stdint.h>

// ===========================================================================
// Problem dims
// ===========================================================================
#define NSEQ 8192
#define DM   1024

// ===========================================================================
// Scratch (device globals — allocation-free rule)
// ===========================================================================
__device__ float g_Xr[(size_t)NSEQ * DM];        // X rounded to tf32
__device__ float g_Wt[3][(size_t)DM * DM];       // W^T rounded  [d_out, d_in]
__device__ float g_Q [(size_t)NSEQ * DM];        // rounded by epilogue
__device__ float g_K [(size_t)NSEQ * DM];        // rounded by epilogue
__device__ float g_V [(size_t)NSEQ * DM];        // fp32
__device__ float g_Vt[(size_t)DM * NSEQ];        // V^T rounded
__device__ float g_P [(size_t)NSEQ * NSEQ];      // exp(scores), tf32-rounded
__device__ float g_psum[64 * (size_t)NSEQ];      // per-n-tile partial row sums
__device__ float g_rowsum[NSEQ];

// ===========================================================================
// Small PTX helpers
// ===========================================================================
__device__ __forceinline__ uint32_t smem_u32(const void* p) {
    uint32_t a;
    asm("{ .reg .u64 t; cvta.to.shared.u64 t, %1; cvt.u32.u64 %0, t; }"
        : "=r"(a) : "l"(p));
    return a;
}
__device__ __forceinline__ float f2tf32f(float f) {
    uint32_t r;
    asm("cvt.rna.tf32.f32 %0, %1;" : "=r"(r) : "f"(f));
    return __uint_as_float(r);
}
__device__ __forceinline__ void cp_async16(uint32_t dst, const float* src) {
    asm volatile("cp.async.cg.shared.global [%0], [%1], 16;"
                 :: "r"(dst), "l"(src));
}
__device__ __forceinline__ void ldsm_x4(uint32_t* r, uint32_t addr) {
    asm volatile("ldmatrix.sync.aligned.m8n8.x4.shared.b16 {%0,%1,%2,%3}, [%4];"
                 : "=r"(r[0]), "=r"(r[1]), "=r"(r[2]), "=r"(r[3]) : "r"(addr));
}
__device__ __forceinline__ void mma_tf32(float* c, const uint32_t* a,
                                         uint32_t b0, uint32_t b1) {
    asm volatile(
        "mma.sync.aligned.m16n8k8.row.col.f32.tf32.tf32.f32 "
        "{%0,%1,%2,%3}, {%4,%5,%6,%7}, {%8,%9}, {%0,%1,%2,%3};"
        : "+f"(c[0]), "+f"(c[1]), "+f"(c[2]), "+f"(c[3])
        : "r"(a[0]), "r"(a[1]), "r"(a[2]), "r"(a[3]), "r"(b0), "r"(b1));
}

// ===========================================================================
// TF32 GEMM (NT): C[M,N] = op( alpha * A[M,K] @ B[N,K]^T )
//   Inputs MUST already be tf32-rounded fp32.
//   BM=128, BN_ in {128, 64}. 256 threads, 8 warps (4 m x 2 n),
//   warp tile 32 x (BN_/2). BK=32, 3-stage cp.async pipeline,
//   prefetch issued BEFORE compute (full-iteration distance).
//   EPI: 0 = alpha*acc
//        1 = round_tf32(acc)                      (alpha=1; Q/K)
//        2 = round_tf32(exp(alpha*acc)) + deterministic partial row sums
//        3 = acc / rowsum[row]
// ===========================================================================
#define BM 128
#define BK 32
#define STAGES 3
#define LDS_STRIDE 36                 // floats; 144B rows; ldmatrix conflict-free

template <int EPI, int BN_>
__global__ __launch_bounds__(256, 2)
void gemm_tf32(const float* __restrict__ A, const float* __restrict__ B,
               float* __restrict__ C, int Kdim, int ldc, float alpha,
               float* __restrict__ psum, const float* __restrict__ rowsum)
{
    constexpr int A_FLOATS = BM * LDS_STRIDE;
    constexpr int B_FLOATS = BN_ * LDS_STRIDE;
    constexpr int STG_FLOATS = A_FLOATS + B_FLOATS;
    constexpr int NTP = BN_ / 32;       // ldsm b-pair count per k8 (4 or 2)
    constexpr int NT  = BN_ / 16;       // acc n-tiles (8 or 4)

    extern __shared__ float smem[];
    const int tid  = threadIdx.x;
    const int lane = tid & 31;
    const int wid  = tid >> 5;
    const int warp_m = wid & 3;        // 0..3 -> M
    const int warp_n = wid >> 2;       // 0..1 -> N
    const int m0 = blockIdx.y * BM;
    const int n0 = blockIdx.x * BN_;

    uint32_t sA[STAGES], sB[STAGES];
    #pragma unroll
    for (int s = 0; s < STAGES; s++) {
        sA[s] = smem_u32(smem + s * STG_FLOATS);
        sB[s] = smem_u32(smem + s * STG_FLOATS + A_FLOATS);
    }

    float acc[2][NT][4];
    #pragma unroll
    for (int mt = 0; mt < 2; mt++)
        #pragma unroll
        for (int nt = 0; nt < NT; nt++)
            #pragma unroll
            for (int j = 0; j < 4; j++) acc[mt][nt][j] = 0.0f;

    // ---- ldmatrix per-lane address offsets (bytes) ----
    const int q  = lane >> 3;
    const int r8 = lane & 7;
    const uint32_t aOff =
        (uint32_t)(((warp_m * 32 + r8 + (q & 1) * 8) * LDS_STRIDE + (q >> 1) * 4) * 4);
    const uint32_t bOff =
        (uint32_t)(((warp_n * (BN_ / 2) + (q >> 1) * 8 + r8) * LDS_STRIDE + (q & 1) * 4) * 4);

    auto load_tile = [&](int buf, int k0) {
        #pragma unroll
        for (int c = 0; c < BM * 8; c += 256) {
            const int cc  = c + tid;
            const int row = cc >> 3;
            const int col = cc & 7;
            cp_async16(sA[buf] + (uint32_t)(row * 144 + col * 16),
                       A + (size_t)(m0 + row) * Kdim + k0 + col * 4);
        }
        #pragma unroll
        for (int c = 0; c < BN_ * 8; c += 256) {
            const int cc  = c + tid;
            const int row = cc >> 3;
            const int col = cc & 7;
            cp_async16(sB[buf] + (uint32_t)(row * 144 + col * 16),
                       B + (size_t)(n0 + row) * Kdim + k0 + col * 4);
        }
        asm volatile("cp.async.commit_group;");
    };

    auto compute = [&](int buf) {
        #pragma unroll
        for (int ks = 0; ks < 4; ks++) {           // four k8 steps
            uint32_t a[2][4];
            #pragma unroll
            for (int mt = 0; mt < 2; mt++)
                ldsm_x4(a[mt], sA[buf] + aOff
                               + (uint32_t)(mt * 16 * LDS_STRIDE * 4 + ks * 32));
            #pragma unroll
            for (int ntp = 0; ntp < NTP; ntp++) {  // nt pairs
                uint32_t b[4];
                ldsm_x4(b, sB[buf] + bOff
                           + (uint32_t)(ntp * 16 * LDS_STRIDE * 4 + ks * 32));
                mma_tf32(acc[0][ntp * 2 + 0], a[0], b[0], b[1]);
                mma_tf32(acc[1][ntp * 2 + 0], a[1], b[0], b[1]);
                mma_tf32(acc[0][ntp * 2 + 1], a[0], b[2], b[3]);
                mma_tf32(acc[1][ntp * 2 + 1], a[1], b[2], b[3]);
            }
        }
    };

    const int KT = Kdim / BK;
    load_tile(0, 0);
    load_tile(1, BK);
    for (int kt = 0; kt < KT; kt++) {
        if (kt + 2 < KT) {
            asm volatile("cp.async.wait_group 1;");
        } else {
            asm volatile("cp.async.wait_group 0;");
        }
        __syncthreads();
        if (kt + 2 < KT) load_tile((kt + 2) % STAGES, (kt + 2) * BK);  // early prefetch
        compute(kt % STAGES);
    }
    __syncthreads();   // before smem reuse in EPI==2

    // ---- epilogue ----
    float rs[2][2];
    rs[0][0] = rs[0][1] = rs[1][0] = rs[1][1] = 0.0f;

    #pragma unroll
    for (int mt = 0; mt < 2; mt++) {
        const int r0 = m0 + warp_m * 32 + mt * 16 + (lane >> 2);
        float inv0 = 1.0f, inv1 = 1.0f;
        if (EPI == 3) {
            inv0 = 1.0f / rowsum[r0];
            inv1 = 1.0f / rowsum[r0 + 8];
        }
        #pragma unroll
        for (int nt = 0; nt < NT; nt++) {
            const int col = n0 + warp_n * (BN_ / 2) + nt * 8 + 2 * (lane & 3);
            float v[4];
            #pragma unroll
            for (int j = 0; j < 4; j++) v[j] = acc[mt][nt][j];
            if (EPI == 0) {
                #pragma unroll
                for (int j = 0; j < 4; j++) v[j] *= alpha;
            } else if (EPI == 1) {
                #pragma unroll
                for (int j = 0; j < 4; j++) v[j] = f2tf32f(v[j]);
            } else if (EPI == 2) {
                #pragma unroll
                for (int j = 0; j < 4; j++) v[j] = __expf(alpha * v[j]);
                rs[mt][0] += v[0] + v[1];
                rs[mt][1] += v[2] + v[3];
                #pragma unroll
                for (int j = 0; j < 4; j++) v[j] = f2tf32f(v[j]);
            } else { // EPI == 3
                v[0] *= inv0; v[1] *= inv0;
                v[2] *= inv1; v[3] *= inv1;
            }
            *(float2*)(C + (size_t)r0 * ldc + col)       = make_float2(v[0], v[1]);
            *(float2*)(C + (size_t)(r0 + 8) * ldc + col) = make_float2(v[2], v[3]);
        }
    }

    if (EPI == 2) {
        // deterministic partial row sums: reduce over lane&3, then over warp_n
        #pragma unroll
        for (int mt = 0; mt < 2; mt++)
            #pragma unroll
            for (int h = 0; h < 2; h++) {
                rs[mt][h] += __shfl_xor_sync(0xFFFFFFFFu, rs[mt][h], 1);
                rs[mt][h] += __shfl_xor_sync(0xFFFFFFFFu, rs[mt][h], 2);
            }
        float* spart = smem;   // [2][128]
        if ((lane & 3) == 0) {
            const int rb = warp_m * 32 + (lane >> 2);
            spart[warp_n * 128 + rb + 0]  = rs[0][0];
            spart[warp_n * 128 + rb + 8]  = rs[0][1];
            spart[warp_n * 128 + rb + 16] = rs[1][0];
            spart[warp_n * 128 + rb + 24] = rs[1][1];
        }
        __syncthreads();
        if (tid < 128)
            psum[(size_t)blockIdx.x * NSEQ + m0 + tid] = spart[tid] + spart[128 + tid];
    }
}

#define SMEM_128 (STAGES * (BM + 128) * LDS_STRIDE * 4)   // 110592 B
#define SMEM_64  (STAGES * (BM +  64) * LDS_STRIDE * 4)   //  82944 B

// ===========================================================================
// Row-sum reduction: rowsum[r] = sum_t psum[t][r]   (64 scores n-tiles)
// ===========================================================================
__global__ __launch_bounds__(256) void rowsum_kernel(
    const float* __restrict__ psum, float* __restrict__ rowsum)
{
    const int r = blockIdx.x * 256 + threadIdx.x;
    float s = 0.0f;
    #pragma unroll 8
    for (int t = 0; t < 64; t++) s += psum[(size_t)t * NSEQ + r];
    rowsum[r] = s;
}

// ===========================================================================
// Elementwise tf32 rounding
// ===========================================================================
__global__ __launch_bounds__(256) void round_kernel(
    const float* __restrict__ src, float* __restrict__ dst, int n4)
{
    int i = blockIdx.x * 256 + threadIdx.x;
    if (i >= n4) return;
    float4 v = *(const float4*)(src + (size_t)i * 4);
    v.x = f2tf32f(v.x); v.y = f2tf32f(v.y);
    v.z = f2tf32f(v.z); v.w = f2tf32f(v.w);
    *(float4*)(dst + (size_t)i * 4) = v;
}

// ===========================================================================
// fp32 transpose: src [R,C] -> dst [C,R], optional tf32 rounding
// ===========================================================================
template <bool ROUND>
__global__ __launch_bounds__(256) void transpose_kernel(
    const float* __restrict__ src, float* __restrict__ dst, int R, int C)
{
    __shared__ float t[32][33];
    const int tx = threadIdx.x, ty = threadIdx.y;   // block (32,8)
    const int bx = blockIdx.x * 32, by = blockIdx.y * 32;
    #pragma unroll
    for (int j = 0; j < 4; j++)
        t[ty + j * 8][tx] = src[(size_t)(by + ty + j * 8) * C + bx + tx];
    __syncthreads();
    #pragma unroll
    for (int j = 0; j < 4; j++) {
        float v = t[tx][ty + j * 8];
        if (ROUND) v = f2tf32f(v);
        dst[(size_t)(bx + ty + j * 8) * R + by + tx] = v;
    }
}

// ===========================================================================
// Launch
// ===========================================================================
extern "C" void kernel_launch(void* const* d_in, const int* in_sizes, int n_in,
                              void* d_out, int out_size)
{
    const float* X  = (const float*)d_in[0];
    const float* Wq = (const float*)d_in[1];
    const float* Wk = (const float*)d_in[2];
    const float* Wv = (const float*)d_in[3];
    float* out = (float*)d_out;

    float *Xr, *Wt, *Q, *K, *V, *Vt, *P, *psum, *rowsum;
    cudaGetSymbolAddress((void**)&Xr, g_Xr);
    cudaGetSymbolAddress((void**)&Wt, g_Wt);
    cudaGetSymbolAddress((void**)&Q,  g_Q);
    cudaGetSymbolAddress((void**)&K,  g_K);
    cudaGetSymbolAddress((void**)&V,  g_V);
    cudaGetSymbolAddress((void**)&Vt, g_Vt);
    cudaGetSymbolAddress((void**)&P,  g_P);
    cudaGetSymbolAddress((void**)&psum,   g_psum);
    cudaGetSymbolAddress((void**)&rowsum, g_rowsum);

    cudaFuncSetAttribute(gemm_tf32<0, 64>,  cudaFuncAttributeMaxDynamicSharedMemorySize, SMEM_64);
    cudaFuncSetAttribute(gemm_tf32<1, 64>,  cudaFuncAttributeMaxDynamicSharedMemorySize, SMEM_64);
    cudaFuncSetAttribute(gemm_tf32<2, 128>, cudaFuncAttributeMaxDynamicSharedMemorySize, SMEM_128);
    cudaFuncSetAttribute(gemm_tf32<3, 64>,  cudaFuncAttributeMaxDynamicSharedMemorySize, SMEM_64);

    const dim3 blk(256);

    // X rounded; W^T rounded
    round_kernel<<<(NSEQ * DM / 4 + 255) / 256, blk>>>(X, Xr, NSEQ * DM / 4);
    {
        dim3 tb(32, 8), tg(DM / 32, DM / 32);
        transpose_kernel<true><<<tg, tb>>>(Wq, Wt + 0 * (size_t)DM * DM, DM, DM);
        transpose_kernel<true><<<tg, tb>>>(Wk, Wt + 1 * (size_t)DM * DM, DM, DM);
        transpose_kernel<true><<<tg, tb>>>(Wv, Wt + 2 * (size_t)DM * DM, DM, DM);
    }

    // Projections (BN=64 tiles: 1024 blocks, good wave balance)
    {
        dim3 g(DM / 64, NSEQ / BM);
        gemm_tf32<1, 64><<<g, blk, SMEM_64>>>(Xr, Wt + 0 * (size_t)DM * DM, Q, DM, DM, 1.0f, nullptr, nullptr);
        gemm_tf32<1, 64><<<g, blk, SMEM_64>>>(Xr, Wt + 1 * (size_t)DM * DM, K, DM, DM, 1.0f, nullptr, nullptr);
        gemm_tf32<0, 64><<<g, blk, SMEM_64>>>(Xr, Wt + 2 * (size_t)DM * DM, V, DM, DM, 1.0f, nullptr, nullptr);
    }

    // V^T rounded
    {
        dim3 tb(32, 8), tg(DM / 32, NSEQ / 32);
        transpose_kernel<true><<<tg, tb>>>(V, Vt, NSEQ, DM);
    }

    // P = exp(Q@K^T / 32) (tf32-rounded) + partial row sums   (BN=128)
    {
        dim3 g(NSEQ / 128, NSEQ / BM);
        gemm_tf32<2, 128><<<g, blk, SMEM_128>>>(Q, K, P, DM, NSEQ, 0.03125f, psum, nullptr);
    }

    // Row sums
    rowsum_kernel<<<NSEQ / 256, blk>>>(psum, rowsum);

    // out = (P @ (V^T)^T) / rowsum   (BN=64 tiles: 1024 blocks)
    {
        dim3 g(DM / 64, NSEQ / BM);
        gemm_tf32<3, 64><<<g, blk, SMEM_64>>>(P, Vt, out, NSEQ, DM, 1.0f, nullptr, rowsum);
    }
}

// round 10
// speedup vs baseline: 1.2349x; 1.2349x over previous
#include <cuda_runtime.h>
#include <math.h>
#include <stdint.h>

// ===========================================================================
// Problem dims
// ===========================================================================
#define NSEQ 8192
#define DM   1024

// ===========================================================================
// Scratch (device globals — allocation-free rule)
// ===========================================================================
__device__ float g_Xr [(size_t)NSEQ * DM];         // X rounded to tf32
__device__ float g_Wt [(size_t)3 * DM * DM];       // [3072,1024] Wq^T|Wk^T|Wv^T rounded
__device__ float g_QKV[(size_t)NSEQ * 3 * DM];     // [8192,3072] Q|K|V rounded
__device__ float g_Vt [(size_t)DM * NSEQ];         // V^T rounded  [1024,8192]
__device__ float g_P  [(size_t)NSEQ * NSEQ];       // exp(scores), tf32-rounded
__device__ float g_psum[64 * (size_t)NSEQ];        // per-n-tile partial row sums
__device__ float g_rowsum[NSEQ];

// ===========================================================================
// Small PTX helpers
// ===========================================================================
__device__ __forceinline__ uint32_t smem_u32(const void* p) {
    uint32_t a;
    asm("{ .reg .u64 t; cvta.to.shared.u64 t, %1; cvt.u32.u64 %0, t; }"
        : "=r"(a) : "l"(p));
    return a;
}
__device__ __forceinline__ float f2tf32f(float f) {
    uint32_t r;
    asm("cvt.rna.tf32.f32 %0, %1;" : "=r"(r) : "f"(f));
    return __uint_as_float(r);
}
__device__ __forceinline__ void cp_async16(uint32_t dst, const float* src) {
    asm volatile("cp.async.cg.shared.global [%0], [%1], 16;"
                 :: "r"(dst), "l"(src));
}
__device__ __forceinline__ void ldsm_x4(uint32_t* r, uint32_t addr) {
    asm volatile("ldmatrix.sync.aligned.m8n8.x4.shared.b16 {%0,%1,%2,%3}, [%4];"
                 : "=r"(r[0]), "=r"(r[1]), "=r"(r[2]), "=r"(r[3]) : "r"(addr));
}
__device__ __forceinline__ void mma_tf32(float* c, const uint32_t* a,
                                         uint32_t b0, uint32_t b1) {
    asm volatile(
        "mma.sync.aligned.m16n8k8.row.col.f32.tf32.tf32.f32 "
        "{%0,%1,%2,%3}, {%4,%5,%6,%7}, {%8,%9}, {%0,%1,%2,%3};"
        : "+f"(c[0]), "+f"(c[1]), "+f"(c[2]), "+f"(c[3])
        : "r"(a[0]), "r"(a[1]), "r"(a[2]), "r"(a[3]), "r"(b0), "r"(b1));
}

// ===========================================================================
// TF32 GEMM (NT): C[M,N] = op( alpha * A[M,K] @ B[N,K]^T ), strided operands.
//   Inputs MUST already be tf32-rounded fp32.
//   128x128 block tile, BK=32, 256 threads (8 warps, 4m x 2n), warp tile 32x64.
//   3-stage cp.async pipeline; round-7 proven ordering (compute, then prefetch).
//   EPI: 1 = round_tf32(acc)                      (alpha=1; QKV)
//        2 = round_tf32(exp(alpha*acc)) + deterministic partial row sums
//        3 = acc / rowsum[row]
// ===========================================================================
#define BM 128
#define BN 128
#define BK 32
#define STAGES 3
#define LDS_STRIDE 36                 // floats; 144B rows; ldmatrix conflict-free
#define BUF_FLOATS (128 * LDS_STRIDE) // 4608
#define GEMM_SMEM_BYTES (2 * STAGES * BUF_FLOATS * 4)  // 110592 B

template <int EPI>
__global__ __launch_bounds__(256, 2)
void gemm_tf32(const float* __restrict__ A, int lda,
               const float* __restrict__ B, int ldb,
               float* __restrict__ C, int ldc,
               int Kdim, float alpha,
               float* __restrict__ psum, const float* __restrict__ rowsum)
{
    extern __shared__ float smem[];
    const int tid  = threadIdx.x;
    const int lane = tid & 31;
    const int wid  = tid >> 5;
    const int warp_m = wid & 3;        // 0..3 -> M
    const int warp_n = wid >> 2;       // 0..1 -> N
    const int m0 = blockIdx.y * BM;
    const int n0 = blockIdx.x * BN;

    uint32_t sA[STAGES], sB[STAGES];
    #pragma unroll
    for (int s = 0; s < STAGES; s++) {
        sA[s] = smem_u32(smem + (2 * s + 0) * BUF_FLOATS);
        sB[s] = smem_u32(smem + (2 * s + 1) * BUF_FLOATS);
    }

    float acc[2][8][4];
    #pragma unroll
    for (int mt = 0; mt < 2; mt++)
        #pragma unroll
        for (int nt = 0; nt < 8; nt++)
            #pragma unroll
            for (int j = 0; j < 4; j++) acc[mt][nt][j] = 0.0f;

    // ---- ldmatrix per-lane address offsets (bytes) ----
    const int q  = lane >> 3;
    const int r8 = lane & 7;
    const uint32_t aOff =
        (uint32_t)(((warp_m * 32 + r8 + (q & 1) * 8) * LDS_STRIDE + (q >> 1) * 4) * 4);
    const uint32_t bOff =
        (uint32_t)(((warp_n * 64 + (q >> 1) * 8 + r8) * LDS_STRIDE + (q & 1) * 4) * 4);

    auto load_tile = [&](int buf, int k0) {
        #pragma unroll
        for (int i = 0; i < 8; i++) {
            const int  c   = tid + (i & 3) * 256;   // 0..1023
            const int  row = c >> 3;                // 0..127
            const int  col = c & 7;                 // 16B chunk in row
            if (i < 4) {
                cp_async16(sA[buf] + (uint32_t)(row * 144 + col * 16),
                           A + (size_t)(m0 + row) * lda + k0 + col * 4);
            } else {
                cp_async16(sB[buf] + (uint32_t)(row * 144 + col * 16),
                           B + (size_t)(n0 + row) * ldb + k0 + col * 4);
            }
        }
        asm volatile("cp.async.commit_group;");
    };

    auto compute = [&](int buf) {
        #pragma unroll
        for (int ks = 0; ks < 4; ks++) {           // four k8 steps
            uint32_t a[2][4];
            #pragma unroll
            for (int mt = 0; mt < 2; mt++)
                ldsm_x4(a[mt], sA[buf] + aOff
                               + (uint32_t)(mt * 16 * LDS_STRIDE * 4 + ks * 32));
            #pragma unroll
            for (int ntp = 0; ntp < 4; ntp++) {    // nt pairs
                uint32_t b[4];
                ldsm_x4(b, sB[buf] + bOff
                           + (uint32_t)(ntp * 16 * LDS_STRIDE * 4 + ks * 32));
                mma_tf32(acc[0][ntp * 2 + 0], a[0], b[0], b[1]);
                mma_tf32(acc[1][ntp * 2 + 0], a[1], b[0], b[1]);
                mma_tf32(acc[0][ntp * 2 + 1], a[0], b[2], b[3]);
                mma_tf32(acc[1][ntp * 2 + 1], a[1], b[2], b[3]);
            }
        }
    };

    const int KT = Kdim / BK;
    load_tile(0, 0);
    load_tile(1, BK);
    for (int kt = 0; kt < KT; kt++) {
        if (kt + 2 < KT) {
            asm volatile("cp.async.wait_group 1;");
        } else {
            asm volatile("cp.async.wait_group 0;");
        }
        __syncthreads();
        compute(kt % STAGES);
        if (kt + 2 < KT) load_tile((kt + 2) % STAGES, (kt + 2) * BK);
    }
    __syncthreads();   // before smem reuse in EPI==2

    // ---- epilogue ----
    float rs[2][2];
    rs[0][0] = rs[0][1] = rs[1][0] = rs[1][1] = 0.0f;

    #pragma unroll
    for (int mt = 0; mt < 2; mt++) {
        const int r0 = m0 + warp_m * 32 + mt * 16 + (lane >> 2);
        float inv0 = 1.0f, inv1 = 1.0f;
        if (EPI == 3) {
            inv0 = 1.0f / rowsum[r0];
            inv1 = 1.0f / rowsum[r0 + 8];
        }
        #pragma unroll
        for (int nt = 0; nt < 8; nt++) {
            const int col = n0 + warp_n * 64 + nt * 8 + 2 * (lane & 3);
            float v[4];
            #pragma unroll
            for (int j = 0; j < 4; j++) v[j] = acc[mt][nt][j];
            if (EPI == 1) {
                #pragma unroll
                for (int j = 0; j < 4; j++) v[j] = f2tf32f(v[j]);
            } else if (EPI == 2) {
                #pragma unroll
                for (int j = 0; j < 4; j++) v[j] = __expf(alpha * v[j]);
                rs[mt][0] += v[0] + v[1];
                rs[mt][1] += v[2] + v[3];
                #pragma unroll
                for (int j = 0; j < 4; j++) v[j] = f2tf32f(v[j]);
            } else { // EPI == 3
                v[0] *= inv0; v[1] *= inv0;
                v[2] *= inv1; v[3] *= inv1;
            }
            *(float2*)(C + (size_t)r0 * ldc + col)       = make_float2(v[0], v[1]);
            *(float2*)(C + (size_t)(r0 + 8) * ldc + col) = make_float2(v[2], v[3]);
        }
    }

    if (EPI == 2) {
        // deterministic partial row sums: reduce over lane&3, then over warp_n
        #pragma unroll
        for (int mt = 0; mt < 2; mt++)
            #pragma unroll
            for (int h = 0; h < 2; h++) {
                rs[mt][h] += __shfl_xor_sync(0xFFFFFFFFu, rs[mt][h], 1);
                rs[mt][h] += __shfl_xor_sync(0xFFFFFFFFu, rs[mt][h], 2);
            }
        float* spart = smem;   // [2][128]
        if ((lane & 3) == 0) {
            const int rb = warp_m * 32 + (lane >> 2);
            spart[warp_n * 128 + rb + 0]  = rs[0][0];
            spart[warp_n * 128 + rb + 8]  = rs[0][1];
            spart[warp_n * 128 + rb + 16] = rs[1][0];
            spart[warp_n * 128 + rb + 24] = rs[1][1];
        }
        __syncthreads();
        if (tid < 128)
            psum[(size_t)blockIdx.x * NSEQ + m0 + tid] = spart[tid] + spart[128 + tid];
    }
}

// ===========================================================================
// Row-sum reduction: rowsum[r] = sum_t psum[t][r]   (64 scores n-tiles)
// ===========================================================================
__global__ __launch_bounds__(256) void rowsum_kernel(
    const float* __restrict__ psum, float* __restrict__ rowsum)
{
    const int r = blockIdx.x * 256 + threadIdx.x;
    float s = 0.0f;
    #pragma unroll 8
    for (int t = 0; t < 64; t++) s += psum[(size_t)t * NSEQ + r];
    rowsum[r] = s;
}

// ===========================================================================
// Elementwise tf32 rounding
// ===========================================================================
__global__ __launch_bounds__(256) void round_kernel(
    const float* __restrict__ src, float* __restrict__ dst, int n4)
{
    int i = blockIdx.x * 256 + threadIdx.x;
    if (i >= n4) return;
    float4 v = *(const float4*)(src + (size_t)i * 4);
    v.x = f2tf32f(v.x); v.y = f2tf32f(v.y);
    v.z = f2tf32f(v.z); v.w = f2tf32f(v.w);
    *(float4*)(dst + (size_t)i * 4) = v;
}

// ===========================================================================
// fp32 transpose with strides: dst[c*ldd + r] = round?(src[r*lds + c])
//   grid: (C/32, R/32), block (32,8)
// ===========================================================================
template <bool ROUND>
__global__ __launch_bounds__(256) void transpose_kernel(
    const float* __restrict__ src, int lds,
    float* __restrict__ dst, int ldd)
{
    __shared__ float t[32][33];
    const int tx = threadIdx.x, ty = threadIdx.y;
    const int bx = blockIdx.x * 32, by = blockIdx.y * 32;
    #pragma unroll
    for (int j = 0; j < 4; j++)
        t[ty + j * 8][tx] = src[(size_t)(by + ty + j * 8) * lds + bx + tx];
    __syncthreads();
    #pragma unroll
    for (int j = 0; j < 4; j++) {
        float v = t[tx][ty + j * 8];
        if (ROUND) v = f2tf32f(v);
        dst[(size_t)(bx + ty + j * 8) * ldd + by + tx] = v;
    }
}

// ===========================================================================
// Launch
// ===========================================================================
extern "C" void kernel_launch(void* const* d_in, const int* in_sizes, int n_in,
                              void* d_out, int out_size)
{
    const float* X  = (const float*)d_in[0];
    const float* Wq = (const float*)d_in[1];
    const float* Wk = (const float*)d_in[2];
    const float* Wv = (const float*)d_in[3];
    float* out = (float*)d_out;

    float *Xr, *Wt, *QKV, *Vt, *P, *psum, *rowsum;
    cudaGetSymbolAddress((void**)&Xr,  g_Xr);
    cudaGetSymbolAddress((void**)&Wt,  g_Wt);
    cudaGetSymbolAddress((void**)&QKV, g_QKV);
    cudaGetSymbolAddress((void**)&Vt,  g_Vt);
    cudaGetSymbolAddress((void**)&P,   g_P);
    cudaGetSymbolAddress((void**)&psum,   g_psum);
    cudaGetSymbolAddress((void**)&rowsum, g_rowsum);

    cudaFuncSetAttribute(gemm_tf32<1>, cudaFuncAttributeMaxDynamicSharedMemorySize, GEMM_SMEM_BYTES);
    cudaFuncSetAttribute(gemm_tf32<2>, cudaFuncAttributeMaxDynamicSharedMemorySize, GEMM_SMEM_BYTES);
    cudaFuncSetAttribute(gemm_tf32<3>, cudaFuncAttributeMaxDynamicSharedMemorySize, GEMM_SMEM_BYTES);

    const dim3 blk(256);

    // X rounded; W^T rounded into contiguous [3072,1024]
    round_kernel<<<(NSEQ * DM / 4 + 255) / 256, blk>>>(X, Xr, NSEQ * DM / 4);
    {
        dim3 tb(32, 8), tg(DM / 32, DM / 32);
        transpose_kernel<true><<<tg, tb>>>(Wq, DM, Wt + 0 * (size_t)DM * DM, DM);
        transpose_kernel<true><<<tg, tb>>>(Wk, DM, Wt + 1 * (size_t)DM * DM, DM);
        transpose_kernel<true><<<tg, tb>>>(Wv, DM, Wt + 2 * (size_t)DM * DM, DM);
    }

    // Fused QKV projection: [8192,3072] = Xr @ Wt3^T   (1536 blocks, 5.2 waves)
    {
        dim3 g(3 * DM / BN, NSEQ / BM);
        gemm_tf32<1><<<g, blk, GEMM_SMEM_BYTES>>>(Xr, DM, Wt, DM,
                                                  QKV, 3 * DM, DM, 1.0f,
                                                  nullptr, nullptr);
    }

    // V^T rounded: [1024,8192] from QKV cols 2048..3071 (round is idempotent)
    {
        dim3 tb(32, 8), tg(DM / 32, NSEQ / 32);
        transpose_kernel<true><<<tg, tb>>>(QKV + 2 * DM, 3 * DM, Vt, NSEQ);
    }

    // P = exp(Q@K^T / 32) (tf32-rounded) + partial row sums
    {
        dim3 g(NSEQ / BN, NSEQ / BM);
        gemm_tf32<2><<<g, blk, GEMM_SMEM_BYTES>>>(QKV + 0 * DM, 3 * DM,
                                                  QKV + 1 * DM, 3 * DM,
                                                  P, NSEQ, DM, 0.03125f,
                                                  psum, nullptr);
    }

    // Row sums
    rowsum_kernel<<<NSEQ / 256, blk>>>(psum, rowsum);

    // out = (P @ (V^T)^T) / rowsum
    {
        dim3 g(DM / BN, NSEQ / BM);
        gemm_tf32<3><<<g, blk, GEMM_SMEM_BYTES>>>(P, NSEQ, Vt, NSEQ,
                                                  out, DM, NSEQ, 1.0f,
                                                  nullptr, rowsum);
    }
}

// round 12
// speedup vs baseline: 2.3054x; 1.8668x over previous
#include <cuda_runtime.h>
#include <cuda_fp16.h>
#include <math.h>
#include <stdint.h>

// ===========================================================================
// Problem dims
// ===========================================================================
#define NSEQ 8192
#define DM   1024

// ===========================================================================
// Scratch (device globals — allocation-free rule)
// ===========================================================================
__device__ __half g_Xh [(size_t)NSEQ * DM];          // X rounded to fp16
__device__ __half g_Wt [(size_t)3 * DM * DM];        // [3072,1024] W^T fp16
__device__ __half g_QKV[(size_t)NSEQ * 3 * DM];      // [8192,3072] Q|K|V fp16
__device__ __half g_Vt [(size_t)DM * NSEQ];          // V^T fp16 [1024,8192]
__device__ __half g_P  [(size_t)NSEQ * NSEQ];        // exp(scores) fp16
__device__ float  g_psum[64 * (size_t)NSEQ];         // per-n-tile partial row sums
__device__ float  g_rowsum[NSEQ];

// ===========================================================================
// Small PTX helpers
// ===========================================================================
__device__ __forceinline__ uint32_t smem_u32(const void* p) {
    uint32_t a;
    asm("{ .reg .u64 t; cvta.to.shared.u64 t, %1; cvt.u32.u64 %0, t; }"
        : "=r"(a) : "l"(p));
    return a;
}
__device__ __forceinline__ void cp_async16(uint32_t dst, const void* src) {
    asm volatile("cp.async.cg.shared.global [%0], [%1], 16;"
                 :: "r"(dst), "l"(src));
}
__device__ __forceinline__ void ldsm_x4(uint32_t* r, uint32_t addr) {
    asm volatile("ldmatrix.sync.aligned.m8n8.x4.shared.b16 {%0,%1,%2,%3}, [%4];"
                 : "=r"(r[0]), "=r"(r[1]), "=r"(r[2]), "=r"(r[3]) : "r"(addr));
}
// fp16 MMA, fp32 accumulate: D = A(16x16) @ B(16x8) + D
__device__ __forceinline__ void mma_f16(float* c, const uint32_t* a,
                                        uint32_t b0, uint32_t b1) {
    asm volatile(
        "mma.sync.aligned.m16n8k16.row.col.f32.f16.f16.f32 "
        "{%0,%1,%2,%3}, {%4,%5,%6,%7}, {%8,%9}, {%0,%1,%2,%3};"
        : "+f"(c[0]), "+f"(c[1]), "+f"(c[2]), "+f"(c[3])
        : "r"(a[0]), "r"(a[1]), "r"(a[2]), "r"(a[3]), "r"(b0), "r"(b1));
}

// ===========================================================================
// FP16 GEMM (NT): C = op( alpha * A[M,K] @ B[N,K]^T ), strided half operands,
// fp32 accumulate.
//   128x128 block tile, BK=64 (four k16 steps), 256 threads, 8 warps (4m x 2n),
//   warp tile 32x64. 3-stage cp.async pipeline (round-7 proven ordering).
//   smem rows: 64 half = 128B data + 16B pad = 144B (ldmatrix conflict-free:
//   8 consecutive rows hit banks r*36%32 = {0,4,...,28}).
//   EPI: 1 = C half = half(acc)                       (QKV projection)
//        2 = C half = half(exp(alpha*acc)) + fp32 deterministic row sums
//        3 = C float = acc / rowsum[row]              (PV)
// ===========================================================================
#define BM 128
#define BN 128
#define BK 64
#define STAGES 3
#define ROW_BYTES 144
#define A_BYTES (BM * ROW_BYTES)          // 18432
#define STG_BYTES (2 * A_BYTES)           // 36864
#define GEMM_SMEM_BYTES (STAGES * STG_BYTES)  // 110592

template <int EPI>
__global__ __launch_bounds__(256, 2)
void gemm_f16(const __half* __restrict__ A, int lda,
              const __half* __restrict__ B, int ldb,
              void* __restrict__ Cv, int ldc,
              int Kdim, float alpha,
              float* __restrict__ psum, const float* __restrict__ rowsum)
{
    extern __shared__ char smem[];
    const uint32_t sbase = smem_u32(smem);
    const int tid  = threadIdx.x;
    const int lane = tid & 31;
    const int wid  = tid >> 5;
    const int warp_m = wid & 3;        // 0..3 -> M
    const int warp_n = wid >> 2;       // 0..1 -> N
    const int m0 = blockIdx.y * BM;
    const int n0 = blockIdx.x * BN;

    uint32_t sA[STAGES], sB[STAGES];
    #pragma unroll
    for (int s = 0; s < STAGES; s++) {
        sA[s] = sbase + s * STG_BYTES;
        sB[s] = sA[s] + A_BYTES;
    }

    float acc[2][8][4];
    #pragma unroll
    for (int mt = 0; mt < 2; mt++)
        #pragma unroll
        for (int nt = 0; nt < 8; nt++)
            #pragma unroll
            for (int j = 0; j < 4; j++) acc[mt][nt][j] = 0.0f;

    // ---- ldmatrix per-lane byte offsets ----
    // A x4 quadrants: (m0-7,k0-7)(m8-15,k0-7)(m0-7,k8-15)(m8-15,k8-15)
    const int q  = lane >> 3;
    const int r8 = lane & 7;
    const uint32_t aOff =
        (uint32_t)((warp_m * 32 + r8 + (q & 1) * 8) * ROW_BYTES + (q >> 1) * 16);
    // B x4 quadrants: (n0-7,k0-7)(n0-7,k8-15)(n8-15,k0-7)(n8-15,k8-15)
    const uint32_t bOff =
        (uint32_t)((warp_n * 64 + (q >> 1) * 8 + r8) * ROW_BYTES + (q & 1) * 16);

    // ---- tile loader: 64 half/row = 8 x 16B chunks, 128 rows per operand ----
    auto load_tile = [&](int buf, int k0) {
        #pragma unroll
        for (int i = 0; i < 8; i++) {
            const int  c   = tid + (i & 3) * 256;   // 0..1023
            const int  row = c >> 3;
            const int  col = c & 7;
            if (i < 4) {
                cp_async16(sA[buf] + (uint32_t)(row * ROW_BYTES + col * 16),
                           A + (size_t)(m0 + row) * lda + k0 + col * 8);
            } else {
                cp_async16(sB[buf] + (uint32_t)(row * ROW_BYTES + col * 16),
                           B + (size_t)(n0 + row) * ldb + k0 + col * 8);
            }
        }
        asm volatile("cp.async.commit_group;");
    };

    auto compute = [&](int buf) {
        #pragma unroll
        for (int ks = 0; ks < 4; ks++) {           // four k16 steps
            uint32_t a[2][4];
            #pragma unroll
            for (int mt = 0; mt < 2; mt++)
                ldsm_x4(a[mt], sA[buf] + aOff
                               + (uint32_t)(mt * 16 * ROW_BYTES + ks * 32));
            #pragma unroll
            for (int ntp = 0; ntp < 4; ntp++) {    // 16 n-cols per pair
                uint32_t b[4];
                ldsm_x4(b, sB[buf] + bOff
                           + (uint32_t)(ntp * 16 * ROW_BYTES + ks * 32));
                mma_f16(acc[0][ntp * 2 + 0], a[0], b[0], b[1]);
                mma_f16(acc[1][ntp * 2 + 0], a[1], b[0], b[1]);
                mma_f16(acc[0][ntp * 2 + 1], a[0], b[2], b[3]);
                mma_f16(acc[1][ntp * 2 + 1], a[1], b[2], b[3]);
            }
        }
    };

    const int KT = Kdim / BK;
    load_tile(0, 0);
    load_tile(1, BK);
    for (int kt = 0; kt < KT; kt++) {
        if (kt + 2 < KT) {
            asm volatile("cp.async.wait_group 1;");
        } else {
            asm volatile("cp.async.wait_group 0;");
        }
        __syncthreads();
        compute(kt % STAGES);
        if (kt + 2 < KT) load_tile((kt + 2) % STAGES, (kt + 2) * BK);
    }
    __syncthreads();   // before smem reuse in EPI==2

    // ---- epilogue ----
    float rs[2][2];
    rs[0][0] = rs[0][1] = rs[1][0] = rs[1][1] = 0.0f;

    __half* Ch = (__half*)Cv;
    float*  Cf = (float*)Cv;

    #pragma unroll
    for (int mt = 0; mt < 2; mt++) {
        const int r0 = m0 + warp_m * 32 + mt * 16 + (lane >> 2);
        float inv0 = 1.0f, inv1 = 1.0f;
        if (EPI == 3) {
            inv0 = 1.0f / rowsum[r0];
            inv1 = 1.0f / rowsum[r0 + 8];
        }
        #pragma unroll
        for (int nt = 0; nt < 8; nt++) {
            const int col = n0 + warp_n * 64 + nt * 8 + 2 * (lane & 3);
            float v[4];
            #pragma unroll
            for (int j = 0; j < 4; j++) v[j] = acc[mt][nt][j];
            if (EPI == 1) {
                *(__half2*)(Ch + (size_t)r0 * ldc + col)       = __floats2half2_rn(v[0], v[1]);
                *(__half2*)(Ch + (size_t)(r0 + 8) * ldc + col) = __floats2half2_rn(v[2], v[3]);
            } else if (EPI == 2) {
                #pragma unroll
                for (int j = 0; j < 4; j++) v[j] = __expf(alpha * v[j]);
                rs[mt][0] += v[0] + v[1];
                rs[mt][1] += v[2] + v[3];
                *(__half2*)(Ch + (size_t)r0 * ldc + col)       = __floats2half2_rn(v[0], v[1]);
                *(__half2*)(Ch + (size_t)(r0 + 8) * ldc + col) = __floats2half2_rn(v[2], v[3]);
            } else { // EPI == 3
                *(float2*)(Cf + (size_t)r0 * ldc + col)       = make_float2(v[0] * inv0, v[1] * inv0);
                *(float2*)(Cf + (size_t)(r0 + 8) * ldc + col) = make_float2(v[2] * inv1, v[3] * inv1);
            }
        }
    }

    if (EPI == 2) {
        // deterministic partial row sums: reduce over lane&3, then over warp_n
        #pragma unroll
        for (int mt = 0; mt < 2; mt++)
            #pragma unroll
            for (int h = 0; h < 2; h++) {
                rs[mt][h] += __shfl_xor_sync(0xFFFFFFFFu, rs[mt][h], 1);
                rs[mt][h] += __shfl_xor_sync(0xFFFFFFFFu, rs[mt][h], 2);
            }
        float* spart = (float*)smem;   // [2][128]
        if ((lane & 3) == 0) {
            const int rb = warp_m * 32 + (lane >> 2);
            spart[warp_n * 128 + rb + 0]  = rs[0][0];
            spart[warp_n * 128 + rb + 8]  = rs[0][1];
            spart[warp_n * 128 + rb + 16] = rs[1][0];
            spart[warp_n * 128 + rb + 24] = rs[1][1];
        }
        __syncthreads();
        if (tid < 128)
            psum[(size_t)blockIdx.x * NSEQ + m0 + tid] = spart[tid] + spart[128 + tid];
    }
}

// ===========================================================================
// Row-sum reduction: rowsum[r] = sum_t psum[t][r]   (64 scores n-tiles)
// ===========================================================================
__global__ __launch_bounds__(256) void rowsum_kernel(
    const float* __restrict__ psum, float* __restrict__ rowsum)
{
    const int r = blockIdx.x * 256 + threadIdx.x;
    float s = 0.0f;
    #pragma unroll 8
    for (int t = 0; t < 64; t++) s += psum[(size_t)t * NSEQ + r];
    rowsum[r] = s;
}

// ===========================================================================
// Elementwise fp32 -> fp16
// ===========================================================================
__global__ __launch_bounds__(256) void f2h_kernel(
    const float* __restrict__ src, __half* __restrict__ dst, int n4)
{
    int i = blockIdx.x * 256 + threadIdx.x;
    if (i >= n4) return;
    float4 v = *(const float4*)(src + (size_t)i * 4);
    __half2 h0 = __floats2half2_rn(v.x, v.y);
    __half2 h1 = __floats2half2_rn(v.z, v.w);
    *(__half2*)(dst + (size_t)i * 4 + 0) = h0;
    *(__half2*)(dst + (size_t)i * 4 + 2) = h1;
}

// ===========================================================================
// Transpose fp32 -> fp16: dst[c*ldd + r] = half(src[r*lds + c])
// grid (C/32, R/32), block (32,8)
// ===========================================================================
__global__ __launch_bounds__(256) void transpose_f2h_kernel(
    const float* __restrict__ src, int lds,
    __half* __restrict__ dst, int ldd)
{
    __shared__ float t[32][33];
    const int tx = threadIdx.x, ty = threadIdx.y;
    const int bx = blockIdx.x * 32, by = blockIdx.y * 32;
    #pragma unroll
    for (int j = 0; j < 4; j++)
        t[ty + j * 8][tx] = src[(size_t)(by + ty + j * 8) * lds + bx + tx];
    __syncthreads();
    #pragma unroll
    for (int j = 0; j < 4; j++)
        dst[(size_t)(bx + ty + j * 8) * ldd + by + tx] = __float2half_rn(t[tx][ty + j * 8]);
}

// ===========================================================================
// Transpose fp16 -> fp16: dst[c*ldd + r] = src[r*lds + c]
// ===========================================================================
__global__ __launch_bounds__(256) void transpose_h2h_kernel(
    const __half* __restrict__ src, int lds,
    __half* __restrict__ dst, int ldd)
{
    __shared__ __half t[32][34];   // 34-half rows: read banks tx*17%32 distinct
    const int tx = threadIdx.x, ty = threadIdx.y;
    const int bx = blockIdx.x * 32, by = blockIdx.y * 32;
    #pragma unroll
    for (int j = 0; j < 4; j++)
        t[ty + j * 8][tx] = src[(size_t)(by + ty + j * 8) * lds + bx + tx];
    __syncthreads();
    #pragma unroll
    for (int j = 0; j < 4; j++)
        dst[(size_t)(bx + ty + j * 8) * ldd + by + tx] = t[tx][ty + j * 8];
}

// ===========================================================================
// Launch
// ===========================================================================
extern "C" void kernel_launch(void* const* d_in, const int* in_sizes, int n_in,
                              void* d_out, int out_size)
{
    const float* X  = (const float*)d_in[0];
    const float* Wq = (const float*)d_in[1];
    const float* Wk = (const float*)d_in[2];
    const float* Wv = (const float*)d_in[3];
    float* out = (float*)d_out;

    __half *Xh, *Wt, *QKV, *Vt, *P;
    float *psum, *rowsum;
    cudaGetSymbolAddress((void**)&Xh,  g_Xh);
    cudaGetSymbolAddress((void**)&Wt,  g_Wt);
    cudaGetSymbolAddress((void**)&QKV, g_QKV);
    cudaGetSymbolAddress((void**)&Vt,  g_Vt);
    cudaGetSymbolAddress((void**)&P,   g_P);
    cudaGetSymbolAddress((void**)&psum,   g_psum);
    cudaGetSymbolAddress((void**)&rowsum, g_rowsum);

    cudaFuncSetAttribute(gemm_f16<1>, cudaFuncAttributeMaxDynamicSharedMemorySize, GEMM_SMEM_BYTES);
    cudaFuncSetAttribute(gemm_f16<2>, cudaFuncAttributeMaxDynamicSharedMemorySize, GEMM_SMEM_BYTES);
    cudaFuncSetAttribute(gemm_f16<3>, cudaFuncAttributeMaxDynamicSharedMemorySize, GEMM_SMEM_BYTES);

    const dim3 blk(256);

    // X -> fp16; W^T -> fp16 contiguous [3072,1024]
    f2h_kernel<<<(NSEQ * DM / 4 + 255) / 256, blk>>>(X, Xh, NSEQ * DM / 4);
    {
        dim3 tb(32, 8), tg(DM / 32, DM / 32);
        transpose_f2h_kernel<<<tg, tb>>>(Wq, DM, Wt + 0 * (size_t)DM * DM, DM);
        transpose_f2h_kernel<<<tg, tb>>>(Wk, DM, Wt + 1 * (size_t)DM * DM, DM);
        transpose_f2h_kernel<<<tg, tb>>>(Wv, DM, Wt + 2 * (size_t)DM * DM, DM);
    }

    // Fused QKV projection: [8192,3072] = Xh @ Wt^T (fp16 out)
    {
        dim3 g(3 * DM / BN, NSEQ / BM);
        gemm_f16<1><<<g, blk, GEMM_SMEM_BYTES>>>(Xh, DM, Wt, DM,
                                                 QKV, 3 * DM, DM, 1.0f,
                                                 nullptr, nullptr);
    }

    // V^T fp16: [1024,8192] from QKV cols 2048..3071
    {
        dim3 tb(32, 8), tg(DM / 32, NSEQ / 32);
        transpose_h2h_kernel<<<tg, tb>>>(QKV + 2 * DM, 3 * DM, Vt, NSEQ);
    }

    // P = half(exp(Q@K^T / 32)) + fp32 partial row sums
    {
        dim3 g(NSEQ / BN, NSEQ / BM);
        gemm_f16<2><<<g, blk, GEMM_SMEM_BYTES>>>(QKV + 0 * DM, 3 * DM,
                                                 QKV + 1 * DM, 3 * DM,
                                                 P, NSEQ, DM, 0.03125f,
                                                 psum, nullptr);
    }

    // Row sums
    rowsum_kernel<<<NSEQ / 256, blk>>>(psum, rowsum);

    // out = (P @ (V^T)^T) / rowsum   (fp32 out)
    {
        dim3 g(DM / BN, NSEQ / BM);
        gemm_f16<3><<<g, blk, GEMM_SMEM_BYTES>>>(P, NSEQ, Vt, NSEQ,
                                                 out, DM, NSEQ, 1.0f,
                                                 nullptr, rowsum);
    }
}